// round 9
// baseline (speedup 1.0000x reference)
#include <cuda_runtime.h>
#include <math.h>

// Problem constants (B=8, L=4096, D=1024, fp32)
#define BB 8
#define LL 4096
#define ND (LL - 1)       // 4095 deltas per batch
#define NI (LL - 2)       // 4094 loss terms per batch
#define TC 56             // terms per block
#define NDEL (TC + 1)     // 57 deltas per block (rows t0 .. t0+57)
#define XBLK 74           // blocks per batch: 74*56 = 4144 >= 4094
// grid = (74, 8) = 592 = 148 SMs * 4 CTAs -> ONE perfectly balanced wave

// Accumulators. Zero-initialized at load; last block resets them each launch.
__device__ float g_ws;
__device__ float g_ms;
__device__ unsigned int g_ticket;

__device__ __forceinline__ float sqnorm_diff(float4 a, float4 b) {
    float dx = a.x - b.x, dy = a.y - b.y, dz = a.z - b.z, dw = a.w - b.w;
    return fmaf(dx, dx, fmaf(dy, dy, fmaf(dz, dz, dw * dw)));
}

// Fused kernel. Block (bx, b) owns terms t in [56*bx, 56*bx+56) ∩ [0, NI).
// Phase 1: SOFTWARE-PIPELINED stream of 58 rows: double-buffered chunks of 4
//          (next chunk's 4 LDG.128 issued BEFORE computing current chunk, so
//          loads are outstanding during the FMA/SHFL drain -> ~100% memory
//          duty cycle). One xor-16 shfl per delta; lanes 0..15 store into
//          s_part[i][warp*16+lane] (57 x 128 floats, ~29 KB).
// Phase 2: warp w reduces deltas i ≡ w (mod 8): 4 LDS + 5 SHFL + sqrt.
// Phase 3: warp 0 computes the 56 weighted loss terms (2 per lane), one
//          atomicAdd pair per block; ticketed last block publishes + resets.
//
// rtp dtype hedge: buffer may be int64 or int32. Read as 16 int32 words;
// little-endian int64 values < 4096 => all odd words zero => take even words.
__global__ __launch_bounds__(256, 4) void fused_kernel(const float* __restrict__ states,
                                                       const float* __restrict__ reasoning_mask,
                                                       const int* __restrict__ rtp_raw,
                                                       float* __restrict__ out) {
    const int b   = blockIdx.y;
    const int t0  = blockIdx.x * TC;
    const int tid = threadIdx.x;
    const int warp = tid >> 5;
    const int lane = tid & 31;
    const unsigned int nblocks = gridDim.x * gridDim.y;

    const float4* __restrict__ base =
        reinterpret_cast<const float4*>(states + (size_t)b * LL * (size_t)1024);

    __shared__ float s_part[NDEL][128];    // 16 half-warp sums per warp-slot
    __shared__ float delta_sm[NDEL];

    const int sp_col = warp * 16 + lane;   // valid when lane < 16
    const bool store_ok = (lane < 16);

    // ---- Phase 1: pipelined stream, 57 deltas = 14 chunks of 4 + 1 tail ----
    if (t0 + NDEL <= LL - 1) {
        float4 buf[2][4];
        // prologue: row t0 (prev) + chunk 0 (rows t0+1 .. t0+4)
        float4 prev = base[(size_t)t0 * 256 + tid];
        #pragma unroll
        for (int j = 0; j < 4; j++)
            buf[0][j] = base[(size_t)(t0 + 1 + j) * 256 + tid];

        #pragma unroll
        for (int ch = 0; ch < 14; ch++) {
            const int cur = ch & 1, nxt = cur ^ 1;
            // issue next chunk's loads BEFORE consuming current chunk
            if (ch < 13) {
                const size_t r = (size_t)(t0 + 1 + 4 * (ch + 1)) * 256 + tid;
                #pragma unroll
                for (int j = 0; j < 4; j++)
                    buf[nxt][j] = base[r + 256 * j];
            } else {
                // tail row t0+57
                buf[nxt][0] = base[(size_t)(t0 + NDEL) * 256 + tid];
            }
            // compute deltas 4*ch .. 4*ch+3
            float s0 = sqnorm_diff(buf[cur][0], prev);
            float s1 = sqnorm_diff(buf[cur][1], buf[cur][0]);
            float s2 = sqnorm_diff(buf[cur][2], buf[cur][1]);
            float s3 = sqnorm_diff(buf[cur][3], buf[cur][2]);
            s0 += __shfl_xor_sync(0xffffffffu, s0, 16);
            s1 += __shfl_xor_sync(0xffffffffu, s1, 16);
            s2 += __shfl_xor_sync(0xffffffffu, s2, 16);
            s3 += __shfl_xor_sync(0xffffffffu, s3, 16);
            if (store_ok) {
                s_part[4 * ch + 0][sp_col] = s0;
                s_part[4 * ch + 1][sp_col] = s1;
                s_part[4 * ch + 2][sp_col] = s2;
                s_part[4 * ch + 3][sp_col] = s3;
            }
            prev = buf[cur][3];
        }
        // tail delta 56 (row t0+57 is in buf[0][0] after ch=13 -> nxt=0)
        float sl = sqnorm_diff(buf[0][0], prev);
        sl += __shfl_xor_sync(0xffffffffu, sl, 16);
        if (store_ok) s_part[NDEL - 1][sp_col] = sl;
    } else {
        // Guarded path (last x-block only): clamp rows; out-of-range deltas
        // become 0 (diff of identical clamped rows) and are unused anyway.
        float4 prev = base[(size_t)t0 * 256 + tid];
        #pragma unroll 4
        for (int i = 0; i < NDEL; i++) {
            int row = t0 + i + 1;
            if (row > LL - 1) row = LL - 1;
            float4 cur = base[(size_t)row * 256 + tid];
            float v = sqnorm_diff(cur, prev);
            v += __shfl_xor_sync(0xffffffffu, v, 16);
            if (store_ok) s_part[i][sp_col] = v;
            prev = cur;
        }
    }

    __syncthreads();

    // ---- Phase 2: reduce 128 partials per delta. Warp w handles deltas
    //      i = w, w+8, ... < NDEL (conflict-free LDS). ----
    for (int i = warp; i < NDEL; i += 8) {
        float v = s_part[i][lane] + s_part[i][lane + 32]
                + s_part[i][lane + 64] + s_part[i][lane + 96];
        #pragma unroll
        for (int o = 16; o > 0; o >>= 1)
            v += __shfl_xor_sync(0xffffffffu, v, o);
        if (lane == 0) delta_sm[i] = sqrtf(v);
    }

    __syncthreads();

    // ---- Phase 3: loss terms, warp 0 only (56 terms, 2 per lane) ----
    if (warp == 0) {
        int odd_or = 0;
        #pragma unroll
        for (int i = 1; i < 16; i += 2) odd_or |= rtp_raw[i];
        const int rtp_b = (odd_or == 0) ? rtp_raw[2 * b] : rtp_raw[b];

        float ws = 0.0f, ms = 0.0f;
        #pragma unroll
        for (int h = 0; h < 2; h++) {
            const int li = lane + 32 * h;     // local term index
            const int t = t0 + li;
            if (li < TC && t < NI) {
                float di = fmaxf(delta_sm[li + 1] - delta_sm[li], 0.0f);
                const float m = reasoning_mask[b * LL + t + 2];
                int dist = rtp_b - t - 2;
                if (dist < 0) dist = 0;
                const float w = (dist < 5) ? (2.0f + (float)(5 - dist) * 0.5f) : 1.0f;
                ws += di * m * w;
                ms += m;
            }
        }
        #pragma unroll
        for (int o = 16; o > 0; o >>= 1) {
            ws += __shfl_xor_sync(0xffffffffu, ws, o);
            ms += __shfl_xor_sync(0xffffffffu, ms, o);
        }
        if (lane == 0) {
            atomicAdd(&g_ws, ws);
            atomicAdd(&g_ms, ms);
            __threadfence();
            const unsigned int my = atomicAdd(&g_ticket, 1u);
            if (my == nblocks - 1u) {
                __threadfence();
                const float tws = *(volatile float*)&g_ws;
                const float tms = *(volatile float*)&g_ms;
                out[0] = tws / (tms + 1e-9f);
                // reset for next graph replay (all blocks done: safe)
                g_ws = 0.0f;
                g_ms = 0.0f;
                g_ticket = 0u;
            }
        }
    }
}

extern "C" void kernel_launch(void* const* d_in, const int* in_sizes, int n_in,
                              void* d_out, int out_size) {
    const float* states = (const float*)d_in[0];
    const float* rmask  = (const float*)d_in[1];
    const int*   rtp    = (const int*)d_in[2];
    float*       out    = (float*)d_out;

    dim3 grid(XBLK, BB);   // (74, 8) = 592 blocks = 148 SMs x 4
    fused_kernel<<<grid, 256>>>(states, rmask, rtp, out);
}